// round 15
// baseline (speedup 1.0000x reference)
#include <cuda_runtime.h>
#include <cuda_fp16.h>
#include <cstdint>

#define NTOK 32768
#define VV 100000
#define NN2 1000
#define NN3 100

#define DA __device__ __align__(256)
DA __half g_Wih2[2048*256];              // rows 0-1023 fwd, 1024-2047 bwd (gate-permuted)
DA __half g_Whhf[1024*256]; DA __half g_Whhb[1024*256];
DA float g_bf[1024]; DA float g_bb[1024];
DA float g_sum2[NN2*256]; DA float g_cnt2[NN2]; DA float g_sum3[NN3*256]; DA float g_cnt3[NN3];
DA __half g_cat[1104*256];               // 0-1000 l2cat, 1001-1101 l3cat, 1102-1103 rootcat
DA float g_P[1104*2048];                 // cat @ [Wihf|Wihb]^T
DA __half g_h1[2*256]; DA float g_c1[2*256]; DA __half g_h2[101*256]; DA float g_c2[101*256];
DA __half g_h3[1001*256]; DA float g_c3[1001*256]; DA float g_HPb[1001*1024];
__device__ int g_i01[101]; __device__ int g_i3[1001];
DA __half g_X0[NTOK*256];
__device__ int g_sidx[NTOK]; __device__ int g_iF3[NTOK]; __device__ int g_iFr[NTOK];
DA __half g_Ha[NTOK*256]; DA float g_Ca[NTOK*256]; DA __half g_Hc[NTOK*256]; DA float g_Cc[NTOK*256];

// ---------------- helpers ----------------
__device__ __forceinline__ float sigf(float x){ return 1.f/(1.f+__expf(-x)); }
__device__ __forceinline__ float tanhfast(float x){
    float y; asm("tanh.approx.f32 %0, %1;" : "=f"(y) : "f"(x)); return y;
}
__device__ __forceinline__ uint32_t stou(const void* p){
    uint32_t a; asm("{ .reg .u64 t; cvta.to.shared.u64 t, %1; cvt.u32.u64 %0, t; }" : "=r"(a) : "l"(p));
    return a;
}
__device__ __forceinline__ void cpa16s(uint32_t saddr, const void* g, int nb){
    asm volatile("cp.async.cg.shared.global [%0], [%1], 16, %2;\n" :: "r"(saddr), "l"(g), "r"(nb));
}
__device__ __forceinline__ void cpa_commit(){ asm volatile("cp.async.commit_group;\n" ::: "memory"); }
template<int N> __device__ __forceinline__ void cpa_wait(){ asm volatile("cp.async.wait_group %0;\n" :: "n"(N) : "memory"); }
__device__ __forceinline__ void ldm4(unsigned &r0, unsigned &r1, unsigned &r2, unsigned &r3, uint32_t a){
    asm volatile("ldmatrix.sync.aligned.m8n8.x4.shared.b16 {%0,%1,%2,%3}, [%4];"
        : "=r"(r0),"=r"(r1),"=r"(r2),"=r"(r3) : "r"(a));
}
__device__ __forceinline__ void mma16(float* d, const unsigned* a, const unsigned* b){
    asm volatile("mma.sync.aligned.m16n8k16.row.col.f32.f16.f16.f32 "
        "{%0,%1,%2,%3},{%4,%5,%6,%7},{%8,%9},{%0,%1,%2,%3};"
        : "+f"(d[0]), "+f"(d[1]), "+f"(d[2]), "+f"(d[3])
        : "r"(a[0]), "r"(a[1]), "r"(a[2]), "r"(a[3]), "r"(b[0]), "r"(b[1]));
}

// ---------------- small kernels ----------------
__global__ void k_zero(){
    int i = blockIdx.x*256 + threadIdx.x;
    if (i < NN2*256) g_sum2[i] = 0.f;
    if (i < NN2)     g_cnt2[i] = 0.f;
    if (i < NN3*256) g_sum3[i] = 0.f;
    if (i < NN3)     g_cnt3[i] = 0.f;
}
// fused both-direction prep: p in [0,2048)
__global__ void k_prep2(const float* wihf, const float* whhf, const float* bihf, const float* bhhf,
                        const float* wihb, const float* whhb, const float* bihb, const float* bhhb){
    int i = blockIdx.x*256 + threadIdx.x;          // over 2048*256
    int p = i >> 8, k = i & 255;
    int q = p & 1023;
    int u = q >> 2, g = q & 3;
    int src = g*256 + u;
    if (p < 1024){
        g_Wih2[(size_t)p*256 + k] = __float2half(wihf[src*256 + k]);
        g_Whhf[(size_t)q*256 + k] = __float2half(whhf[src*256 + k]);
        if (k == 0) g_bf[q] = bihf[src] + bhhf[src];
    } else {
        g_Wih2[(size_t)p*256 + k] = __float2half(wihb[src*256 + k]);
        g_Whhb[(size_t)q*256 + k] = __float2half(whhb[src*256 + k]);
        if (k == 0) g_bb[q] = bihb[src] + bhhb[src];
    }
}
__global__ void k_seg2(const float* __restrict__ embed, const int* __restrict__ l2){
    int gsz = gridDim.x*blockDim.x;
    for (int s = blockIdx.x*blockDim.x + threadIdx.x; s < VV*64; s += gsz){
        int leaf = s >> 6, q = s & 63;
        if (leaf == 0) continue;
        int j = l2[leaf];
        float4 v = ((const float4*)(embed + (size_t)leaf*256))[q];
        float* dst = g_sum2 + j*256 + q*4;
        atomicAdd(dst+0, v.x); atomicAdd(dst+1, v.y);
        atomicAdd(dst+2, v.z); atomicAdd(dst+3, v.w);
        if (q == 0) atomicAdd(&g_cnt2[j], 1.f);
    }
}
__global__ void k_lvl2(const int* l3){
    int j = blockIdx.x, d = threadIdx.x;
    if (j == 1000){ g_cat[j*256 + d] = __float2half(0.f); return; }
    float c = fmaxf(g_cnt2[j], 1.f);
    float v = g_sum2[j*256 + d] / c;
    g_cat[j*256 + d] = __float2half(v);
    int k = l3[j];
    atomicAdd(&g_sum3[k*256 + d], v);
    if (d == 0) atomicAdd(&g_cnt3[k], 1.f);
}
__global__ void k_lvl3(){
    int k = blockIdx.x, d = threadIdx.x;
    if (k == 100){ g_cat[(1001+k)*256 + d] = __float2half(0.f); return; }
    float c = fmaxf(g_cnt3[k], 1.f);
    g_cat[(1001+k)*256 + d] = __float2half(g_sum3[k*256 + d] / c);
}
__global__ void k_root(){
    int d = threadIdx.x;
    float s = 0.f;
    #pragma unroll 4
    for (int k = 0; k < 100; k++) s += __half2float(g_cat[(1001+k)*256 + d]);
    g_cat[1102*256 + d] = __float2half(s * 0.01f);
    g_cat[1103*256 + d] = __float2half(0.f);
}
__global__ void k_bidx(const int* l3){
    int i = blockIdx.x*256 + threadIdx.x;
    if (i < 101)  g_i01[i] = (i < 100) ? 0 : 1;
    if (i < 1001) g_i3[i]  = (i < 1000) ? l3[i] : 100;
}
__global__ void k_tok(const int* __restrict__ src, const int* __restrict__ l2,
                      const int* __restrict__ l3, const float* __restrict__ embed){
    int gsz = gridDim.x*blockDim.x;
    for (int s = blockIdx.x*blockDim.x + threadIdx.x; s < NTOK*64; s += gsz){
        int t = s >> 6, q = s & 63;
        int tok = __ldg(&src[t]);
        float4 v = make_float4(0.f,0.f,0.f,0.f);
        if (tok != 0) v = ((const float4*)(embed + (size_t)tok*256))[q];
        __half2 a = __floats2half2_rn(v.x, v.y), b = __floats2half2_rn(v.z, v.w);
        uint2 w; w.x = *(unsigned*)&a; w.y = *(unsigned*)&b;
        ((uint2*)(g_X0 + (size_t)t*256))[q] = w;
        if (q == 0){
            bool msk = (tok == 0);
            g_sidx[t] = msk ? 1000 : l2[tok];
            g_iF3[t]  = msk ? 100 : l3[l2[tok]];
            g_iFr[t]  = msk ? 1 : 0;
        }
    }
}

// ---------------- barrier-free warp-independent fp16 GEMM + fused LSTM -------
// C[M,nTotal] tile: CTA 128x64, 8 warps; B stride 528 (LDSM conflict-free);
// per-warp 4-stage cp.async A pipeline; fully unrolled K loop; 3 CTAs/SM.
#define B_STRIDE 528
#define B_BYTES  (64*B_STRIDE)           // 33792
#define AW_BYTES (4*1280)                // per warp: 4 stages x 1280B
#define SMEMB    (B_BYTES + 8*AW_BYTES)  // 74752

__global__ void __launch_bounds__(256,3) k_gemm(
    const __half* __restrict__ A, const int* __restrict__ aIdx,
    const __half* __restrict__ W,
    const float* __restrict__ Xadd, const int* __restrict__ xIdx, int xStride,
    const float* __restrict__ bias,
    const float* __restrict__ Cprev, const int* __restrict__ cIdx,
    void* HoutV, int hStride, int hOff, float* Cout,
    float* Zout, int zStride, int halfH, int M)
{
    extern __shared__ __align__(16) char sm[];
    const int tid = threadIdx.x, warp = tid >> 5, lane = tid & 31;
    const int m0 = blockIdx.x*128, n0 = blockIdx.y*64;
    const uint32_t sbase = stou(sm);
    const uint32_t awbase = sbase + B_BYTES + warp*AW_BYTES;

    // ---- B cooperative load: 64 rows x 256 K halfs ----
    #pragma unroll
    for (int i = 0; i < 8; i++){
        int slot = tid + i*256;
        int row = slot >> 5, c16 = slot & 31;
        cpa16s(sbase + row*B_STRIDE + c16*16, W + (size_t)(n0 + row)*256 + c16*8, 16);
    }
    cpa_commit();

    // ---- per-warp A strip slots ----
    const __half* agp[2]; int ab[2]; uint32_t adst[2];
    #pragma unroll
    for (int i = 0; i < 2; i++){
        int slot = lane + i*32;
        int r16 = slot >> 2, c16 = slot & 3;
        int grow = m0 + warp*16 + r16;
        int ar = 0; ab[i] = 0;
        if (grow < M){ ar = aIdx ? aIdx[grow] : grow; ab[i] = 16; }
        agp[i] = A + (size_t)ar*256 + c16*8;
        adst[i] = (uint32_t)(r16*80 + c16*16);
    }
    auto prefetch = [&](int c, int st){
        uint32_t b0 = awbase + (uint32_t)st*1280;
        cpa16s(b0 + adst[0], agp[0] + c*32, ab[0]);
        cpa16s(b0 + adst[1], agp[1] + c*32, ab[1]);
        cpa_commit();
    };

    prefetch(0, 0);
    prefetch(1, 1);
    prefetch(2, 2);
    cpa_wait<3>();                                 // B complete (3 A groups may remain)
    __syncthreads();

    const uint32_t aoff = (uint32_t)((lane & 15)*80 + (lane >> 4)*16);
    const uint32_t laneB = (uint32_t)(((((lane >> 3) & 2) << 2) + (lane & 7))*B_STRIDE
                                      + ((lane >> 3) & 1)*16);

    float acc[8][4];
    #pragma unroll
    for (int nt=0;nt<8;nt++)
        #pragma unroll
        for (int q=0;q<4;q++) acc[nt][q] = 0.f;

    #pragma unroll
    for (int c = 0; c < 8; c++){
        if (c < 6) cpa_wait<2>(); else if (c == 6) cpa_wait<1>(); else cpa_wait<0>();
        __syncwarp();
        uint32_t abase = awbase + (uint32_t)(c & 3)*1280;
        uint32_t bko = (uint32_t)c*64;
        #pragma unroll
        for (int ks = 0; ks < 2; ks++){
            unsigned a[4];
            ldm4(a[0], a[1], a[2], a[3], abase + aoff + ks*32);
            #pragma unroll
            for (int ntp = 0; ntp < 4; ntp++){
                unsigned bb[4];
                ldm4(bb[0], bb[1], bb[2], bb[3],
                     sbase + laneB + ntp*(16*B_STRIDE) + bko + ks*32);
                mma16(acc[2*ntp],   a, bb + 0);
                mma16(acc[2*ntp+1], a, bb + 2);
            }
        }
        if (c + 3 < 8) prefetch(c + 3, (c + 3) & 3);
    }

    // ---- epilogue: smem reused as per-warp slabs ----
    __syncthreads();
    const int gid = lane >> 2, tg = lane & 3;
    float* slab = (float*)sm + warp*1088;          // 16 rows x 68 floats
    #pragma unroll
    for (int nt = 0; nt < 8; nt++){
        int cc = nt*8 + tg*2;
        slab[gid*68 + cc]       = acc[nt][0];
        slab[gid*68 + cc + 1]   = acc[nt][1];
        slab[(gid+8)*68 + cc]   = acc[nt][2];
        slab[(gid+8)*68 + cc+1] = acc[nt][3];
    }
    __syncwarp();

    const int u = lane & 15, rh = lane >> 4;
    float4 b4 = make_float4(0.f,0.f,0.f,0.f);
    if (!Zout) b4 = ((const float4*)(bias + n0))[u];
    #pragma unroll 1
    for (int it = 0; it < 8; it++){
        int r = it*2 + rh;
        int grow = m0 + warp*16 + r;
        if (grow >= M) continue;
        float4 z = ((const float4*)(slab + r*68))[u];
        if (Zout){
            ((float4*)(Zout + (size_t)grow*zStride + n0))[u] = z;
        } else {
            z.x += b4.x; z.y += b4.y; z.z += b4.z; z.w += b4.w;
            if (Xadd){
                int xr = xIdx ? xIdx[grow] : grow;
                float4 x4 = ((const float4*)(Xadd + (size_t)xr*xStride + n0))[u];
                z.x += x4.x; z.y += x4.y; z.z += x4.z; z.w += x4.w;
            }
            int unit = (n0 >> 2) + u;
            float cp = 0.f;
            if (Cprev){
                int cr = cIdx ? cIdx[grow] : grow;
                cp = Cprev[(size_t)cr*256 + unit];
            }
            float cv = sigf(z.y)*cp + sigf(z.x)*tanhfast(z.z);
            float hv = sigf(z.w)*tanhfast(cv);
            if (halfH) ((__half*)HoutV)[(size_t)grow*hStride + hOff + unit] = __float2half(hv);
            else       ((float*)HoutV)[(size_t)grow*hStride + hOff + unit] = hv;
            if (Cout) Cout[(size_t)grow*256 + unit] = cv;
        }
    }
}

// ---------------- host ----------------
static void* sym(const void* s){ void* p = nullptr; cudaGetSymbolAddress(&p, s); return p; }

extern "C" void kernel_launch(void* const* d_in, const int* in_sizes, int n_in,
                              void* d_out, int out_size)
{
    const int*   src   = (const int*)  d_in[0];
    const int*   l2    = (const int*)  d_in[1];
    const int*   l3    = (const int*)  d_in[2];
    const float* embed = (const float*)d_in[3];
    const float* wihf  = (const float*)d_in[4];
    const float* whhf  = (const float*)d_in[5];
    const float* bihf  = (const float*)d_in[6];
    const float* bhhf  = (const float*)d_in[7];
    const float* wihb  = (const float*)d_in[8];
    const float* whhb  = (const float*)d_in[9];
    const float* bihb  = (const float*)d_in[10];
    const float* bhhb  = (const float*)d_in[11];
    float* out = (float*)d_out;

    cudaFuncSetAttribute(k_gemm, cudaFuncAttributeMaxDynamicSharedMemorySize, SMEMB);

    static cudaStream_t s1 = nullptr;
    static cudaEvent_t evPrep, evX0, evPf, evJoin;
    if (!s1){
        cudaStreamCreateWithFlags(&s1, cudaStreamNonBlocking);
        cudaEventCreateWithFlags(&evPrep, cudaEventDisableTiming);
        cudaEventCreateWithFlags(&evX0,  cudaEventDisableTiming);
        cudaEventCreateWithFlags(&evPf,  cudaEventDisableTiming);
        cudaEventCreateWithFlags(&evJoin,cudaEventDisableTiming);
    }

    __half *Wih2=(__half*)sym(g_Wih2);
    __half *Whhf=(__half*)sym(g_Whhf), *Whhb=(__half*)sym(g_Whhb);
    float *bf=(float*)sym(g_bf), *bb=(float*)sym(g_bb);
    __half *cat=(__half*)sym(g_cat);
    float *P=(float*)sym(g_P);
    __half *h1=(__half*)sym(g_h1), *h2=(__half*)sym(g_h2), *h3=(__half*)sym(g_h3);
    float *c1=(float*)sym(g_c1), *c2=(float*)sym(g_c2), *c3=(float*)sym(g_c3);
    float *HPb=(float*)sym(g_HPb);
    int *i01=(int*)sym(g_i01), *i3=(int*)sym(g_i3);
    __half *X0=(__half*)sym(g_X0);
    int *sidx=(int*)sym(g_sidx), *iF3=(int*)sym(g_iF3), *iFr=(int*)sym(g_iFr);
    __half *Ha=(__half*)sym(g_Ha), *Hc=(__half*)sym(g_Hc);
    float *Ca=(float*)sym(g_Ca), *Cc=(float*)sym(g_Cc);

    __half *Wihf = Wih2;                 // rows 0-1023
    __half *Wihb = Wih2 + 1024*256;      // rows 1024-2047
    float  *P3base = P + (size_t)1001*2048;
    float  *Prbase = P + (size_t)1102*2048;

    dim3 gBig(256,16), gCat(9,32), gS1(1,16), gS101(1,16), gS1001(8,16);

    // ---- side stream s1: tree means (independent of weights) ----
    k_zero<<<1000,256,0,s1>>>();
    k_seg2<<<2048,256,0,s1>>>(embed, l2);
    k_lvl2<<<1001,256,0,s1>>>(l3);
    k_lvl3<<<101,256,0,s1>>>();
    k_root<<<1,256,0,s1>>>();
    k_bidx<<<5,256,0,s1>>>(l3);

    // ---- stream 0: fused weight prep + tokenize ----
    k_prep2<<<2048,256>>>(wihf, whhf, bihf, bhhf, wihb, whhb, bihb, bhhb);
    cudaEventRecord(evPrep, 0);
    k_tok<<<1024,256>>>(src, l2, l3, embed);
    cudaEventRecord(evX0, 0);

    // BIG 1: forward step 1 (x=E[tok])
    k_gemm<<<gBig,256,SMEMB>>>(X0, 0, Wihf, 0,0,0, bf, 0,0, Ha,256,0, Ca, 0,0, 1, NTOK);

    // ---- side stream s1: merged P-table GEMM + backward chain + bigB ----
    cudaStreamWaitEvent(s1, evPrep, 0);
    k_gemm<<<gCat,256,SMEMB,s1>>>(cat, 0, Wih2, 0,0,0, 0, 0,0, 0,0,0, 0, P, 2048, 0, 1104);
    cudaEventRecord(evPf, s1);

    k_gemm<<<gS1   ,256,SMEMB,s1>>>(cat + (size_t)1102*256, 0, Wihb, 0,0,0,         bb, 0,0,    h1,256,0, c1, 0,0, 1, 2);
    k_gemm<<<gS101 ,256,SMEMB,s1>>>(h1, i01, Whhb, P3base + 1024, 0, 2048,          bb, c1,i01, h2,256,0, c2, 0,0, 1, 101);
    k_gemm<<<gS1001,256,SMEMB,s1>>>(h2, i3,  Whhb, P + 1024,      0, 2048,          bb, c2,i3,  h3,256,0, c3, 0,0, 1, 1001);
    k_gemm<<<gS1001,256,SMEMB,s1>>>(h3, 0,   Whhb, 0,0,0, 0, 0,0, 0,0,0, 0, HPb, 1024, 0, 1001);

    cudaStreamWaitEvent(s1, evX0, 0);
    k_gemm<<<gBig,256,SMEMB,s1>>>(X0, 0, Wihb, HPb, sidx, 1024, bb, c3, sidx, out,512,256, 0, 0,0, 0, NTOK);
    cudaEventRecord(evJoin, s1);

    // ---- stream 0: forward steps 2-4 ----
    cudaStreamWaitEvent(0, evPf, 0);
    k_gemm<<<gBig,256,SMEMB>>>(Ha, 0, Whhf, P,      sidx, 2048, bf, Ca,0, Hc,256,0, Cc, 0,0, 1, NTOK);
    k_gemm<<<gBig,256,SMEMB>>>(Hc, 0, Whhf, P3base, iF3,  2048, bf, Cc,0, Ha,256,0, Ca, 0,0, 1, NTOK);
    k_gemm<<<gBig,256,SMEMB>>>(Ha, 0, Whhf, Prbase, iFr,  2048, bf, Ca,0, out,512,0, 0, 0,0, 0, NTOK);

    cudaStreamWaitEvent(0, evJoin, 0);
}

// round 17
// speedup vs baseline: 1.1076x; 1.1076x over previous
#include <cuda_runtime.h>
#include <cuda_fp16.h>
#include <cstdint>

#define NTOK 32768
#define VV 100000
#define NN2 1000
#define NN3 100

#define DA __device__ __align__(256)
DA __half g_Wih2[2048*256];              // rows 0-1023 fwd, 1024-2047 bwd (gate-permuted)
DA __half g_Whhf[1024*256]; DA __half g_Whhb[1024*256];
DA float g_bf[1024]; DA float g_bb[1024];
DA float g_sum2[NN2*256]; DA float g_cnt2[NN2]; DA float g_sum3[NN3*256]; DA float g_cnt3[NN3];
DA __half g_cat[1104*256];               // 0-1000 l2cat, 1001-1101 l3cat, 1102-1103 rootcat
DA float g_P[1104*2048];                 // cat @ [Wihf|Wihb]^T
DA __half g_h1[2*256]; DA float g_c1[2*256]; DA __half g_h2[101*256]; DA float g_c2[101*256];
DA __half g_h3[1001*256]; DA float g_c3[1001*256]; DA float g_HPb[1001*1024];
__device__ int g_i01[101]; __device__ int g_i3[1001];
DA __half g_X0[NTOK*256];
__device__ int g_sidx[NTOK]; __device__ int g_iF3[NTOK]; __device__ int g_iFr[NTOK];
DA __half g_Ha[NTOK*256]; DA float g_Ca[NTOK*256]; DA __half g_Hc[NTOK*256]; DA float g_Cc[NTOK*256];
// dedup structures + compact results
__device__ int g_map[VV]; __device__ int g_uniq[NTOK]; __device__ int g_cnt;
DA float g_resF[NTOK*256]; DA float g_resB[NTOK*256];

// ---------------- helpers ----------------
__device__ __forceinline__ float sigf(float x){ return 1.f/(1.f+__expf(-x)); }
__device__ __forceinline__ float tanhfast(float x){
    float y; asm("tanh.approx.f32 %0, %1;" : "=f"(y) : "f"(x)); return y;
}
__device__ __forceinline__ uint32_t stou(const void* p){
    uint32_t a; asm("{ .reg .u64 t; cvta.to.shared.u64 t, %1; cvt.u32.u64 %0, t; }" : "=r"(a) : "l"(p));
    return a;
}
__device__ __forceinline__ void cpa16s(uint32_t saddr, const void* g, int nb){
    asm volatile("cp.async.cg.shared.global [%0], [%1], 16, %2;\n" :: "r"(saddr), "l"(g), "r"(nb));
}
__device__ __forceinline__ void cpa_commit(){ asm volatile("cp.async.commit_group;\n" ::: "memory"); }
template<int N> __device__ __forceinline__ void cpa_wait(){ asm volatile("cp.async.wait_group %0;\n" :: "n"(N) : "memory"); }
__device__ __forceinline__ void ldm4(unsigned &r0, unsigned &r1, unsigned &r2, unsigned &r3, uint32_t a){
    asm volatile("ldmatrix.sync.aligned.m8n8.x4.shared.b16 {%0,%1,%2,%3}, [%4];"
        : "=r"(r0),"=r"(r1),"=r"(r2),"=r"(r3) : "r"(a));
}
__device__ __forceinline__ void mma16(float* d, const unsigned* a, const unsigned* b){
    asm volatile("mma.sync.aligned.m16n8k16.row.col.f32.f16.f16.f32 "
        "{%0,%1,%2,%3},{%4,%5,%6,%7},{%8,%9},{%0,%1,%2,%3};"
        : "+f"(d[0]), "+f"(d[1]), "+f"(d[2]), "+f"(d[3])
        : "r"(a[0]), "r"(a[1]), "r"(a[2]), "r"(a[3]), "r"(b[0]), "r"(b[1]));
}

// ---------------- small kernels ----------------
__global__ void k_zero(){
    int i = blockIdx.x*256 + threadIdx.x;
    if (i < NN2*256) g_sum2[i] = 0.f;
    if (i < NN2)     g_cnt2[i] = 0.f;
    if (i < NN3*256) g_sum3[i] = 0.f;
    if (i < NN3)     g_cnt3[i] = 0.f;
}
__global__ void k_prep(const float* wih, const float* whh, const float* bih, const float* bhh,
                       __half* wihP, __half* whhP, float* bP){
    int i = blockIdx.x*256 + threadIdx.x;
    int p = i >> 8, k = i & 255;
    int u = p >> 2, g = p & 3;
    int src = g*256 + u;
    wihP[p*256 + k] = __float2half(wih[src*256 + k]);
    whhP[p*256 + k] = __float2half(whh[src*256 + k]);
    if (k == 0) bP[p] = bih[src] + bhh[src];
}
__global__ void k_seg2(const float* __restrict__ embed, const int* __restrict__ l2){
    int gsz = gridDim.x*blockDim.x;
    for (int s = blockIdx.x*blockDim.x + threadIdx.x; s < VV*64; s += gsz){
        int leaf = s >> 6, q = s & 63;
        if (leaf == 0) continue;
        int j = l2[leaf];
        float4 v = ((const float4*)(embed + (size_t)leaf*256))[q];
        float* dst = g_sum2 + j*256 + q*4;
        atomicAdd(dst+0, v.x); atomicAdd(dst+1, v.y);
        atomicAdd(dst+2, v.z); atomicAdd(dst+3, v.w);
        if (q == 0) atomicAdd(&g_cnt2[j], 1.f);
    }
}
__global__ void k_lvl2(const int* l3){
    int j = blockIdx.x, d = threadIdx.x;
    if (j == 1000){ g_cat[j*256 + d] = __float2half(0.f); return; }
    float c = fmaxf(g_cnt2[j], 1.f);
    float v = g_sum2[j*256 + d] / c;
    g_cat[j*256 + d] = __float2half(v);
    int k = l3[j];
    atomicAdd(&g_sum3[k*256 + d], v);
    if (d == 0) atomicAdd(&g_cnt3[k], 1.f);
}
__global__ void k_lvl3(){
    int k = blockIdx.x, d = threadIdx.x;
    if (k == 100){ g_cat[(1001+k)*256 + d] = __float2half(0.f); return; }
    float c = fmaxf(g_cnt3[k], 1.f);
    g_cat[(1001+k)*256 + d] = __float2half(g_sum3[k*256 + d] / c);
}
__global__ void k_root(){
    int d = threadIdx.x;
    float s = 0.f;
    #pragma unroll 4
    for (int k = 0; k < 100; k++) s += __half2float(g_cat[(1001+k)*256 + d]);
    g_cat[1102*256 + d] = __float2half(s * 0.01f);
    g_cat[1103*256 + d] = __float2half(0.f);
}
__global__ void k_bidx(const int* l3){
    int i = blockIdx.x*256 + threadIdx.x;
    if (i < 101)  g_i01[i] = (i < 100) ? 0 : 1;
    if (i < 1001) g_i3[i]  = (i < 1000) ? l3[i] : 100;
}
// ---- dedup ----
__global__ void k_mapinit(){
    int i = blockIdx.x*256 + threadIdx.x;
    if (i < VV) g_map[i] = -1;
    if (i == 0) g_cnt = 0;
}
__global__ void k_claim(const int* __restrict__ src){
    int t = blockIdx.x*256 + threadIdx.x;
    if (t >= NTOK) return;
    int tok = src[t];
    if (atomicCAS(&g_map[tok], -1, -2) == -1){
        int id = atomicAdd(&g_cnt, 1);
        g_uniq[id] = tok;
        g_map[tok] = id;
    }
}
// per-unique tokenize (bounded by device count)
__global__ void k_tok2(const int* __restrict__ l2, const int* __restrict__ l3,
                       const float* __restrict__ embed){
    int nu = g_cnt;
    int gsz = gridDim.x*blockDim.x;
    for (int s = blockIdx.x*blockDim.x + threadIdx.x; ; s += gsz){
        int u = s >> 6;
        if (u >= nu) return;
        int q = s & 63;
        int tok = g_uniq[u];
        float4 v = make_float4(0.f,0.f,0.f,0.f);
        if (tok != 0) v = ((const float4*)(embed + (size_t)tok*256))[q];
        __half2 a = __floats2half2_rn(v.x, v.y), b = __floats2half2_rn(v.z, v.w);
        uint2 w; w.x = *(unsigned*)&a; w.y = *(unsigned*)&b;
        ((uint2*)(g_X0 + (size_t)u*256))[q] = w;
        if (q == 0){
            bool msk = (tok == 0);
            g_sidx[u] = msk ? 1000 : l2[tok];
            g_iF3[u]  = msk ? 100 : l3[l2[tok]];
            g_iFr[u]  = msk ? 1 : 0;
        }
    }
}
// expand compact results to all tokens: out[t] = [resF[id] | resB[id]]
__global__ void k_expand(const int* __restrict__ src, float* __restrict__ out){
    int gsz = gridDim.x*blockDim.x;
    for (int s = blockIdx.x*blockDim.x + threadIdx.x; s < NTOK*128; s += gsz){
        int t = s >> 7, q = s & 127;
        int id = g_map[src[t]];
        float4 v = (q < 64) ? ((const float4*)(g_resF + (size_t)id*256))[q]
                            : ((const float4*)(g_resB + (size_t)id*256))[q - 64];
        ((float4*)(out + (size_t)t*512))[q] = v;
    }
}

// ---------------- barrier-free warp-independent fp16 GEMM + fused LSTM -------
// C[M,nTotal] tile: CTA 128x64, 8 warps; B stride 528 (LDSM conflict-free);
// per-warp 3-stage cp.async A pipeline; fully unrolled K loop; 3 CTAs/SM.
// Mdev (optional) overrides M from device memory; CTAs beyond M exit early.
#define B_STRIDE 528
#define B_BYTES  (64*B_STRIDE)           // 33792
#define AW_BYTES (3*1280)                // per warp: 3 stages x 1280B
#define SMEMB    (B_BYTES + 8*AW_BYTES)  // 64512

__global__ void __launch_bounds__(256,3) k_gemm(
    const __half* __restrict__ A, const int* __restrict__ aIdx,
    const __half* __restrict__ W,
    const float* __restrict__ Xadd, const int* __restrict__ xIdx, int xStride,
    const float* __restrict__ bias,
    const float* __restrict__ Cprev, const int* __restrict__ cIdx,
    void* HoutV, int hStride, int hOff, float* Cout,
    float* Zout, int zStride, int halfH, int M, const int* Mdev)
{
    extern __shared__ __align__(16) char sm[];
    const int tid = threadIdx.x, warp = tid >> 5, lane = tid & 31;
    const int m0 = blockIdx.x*128, n0 = blockIdx.y*64;
    if (Mdev) M = __ldg(Mdev);
    if (m0 >= M) return;
    const uint32_t sbase = stou(sm);
    const uint32_t awbase = sbase + B_BYTES + warp*AW_BYTES;

    // ---- B cooperative load: 64 rows x 256 K halfs ----
    #pragma unroll
    for (int i = 0; i < 8; i++){
        int slot = tid + i*256;
        int row = slot >> 5, c16 = slot & 31;
        cpa16s(sbase + row*B_STRIDE + c16*16, W + (size_t)(n0 + row)*256 + c16*8, 16);
    }
    cpa_commit();

    // ---- per-warp A strip slots ----
    const __half* agp[2]; int ab[2]; uint32_t adst[2];
    #pragma unroll
    for (int i = 0; i < 2; i++){
        int slot = lane + i*32;
        int r16 = slot >> 2, c16 = slot & 3;
        int grow = m0 + warp*16 + r16;
        int ar = 0; ab[i] = 0;
        if (grow < M){ ar = aIdx ? aIdx[grow] : grow; ab[i] = 16; }
        agp[i] = A + (size_t)ar*256 + c16*8;
        adst[i] = (uint32_t)(r16*80 + c16*16);
    }
    auto prefetch = [&](int c, int st){
        uint32_t b0 = awbase + (uint32_t)st*1280;
        cpa16s(b0 + adst[0], agp[0] + c*32, ab[0]);
        cpa16s(b0 + adst[1], agp[1] + c*32, ab[1]);
        cpa_commit();
    };

    prefetch(0, 0);
    prefetch(1, 1);
    cpa_wait<2>();                                 // B complete
    __syncthreads();

    const uint32_t aoff = (uint32_t)((lane & 15)*80 + (lane >> 4)*16);
    const uint32_t laneB = (uint32_t)(((((lane >> 3) & 2) << 2) + (lane & 7))*B_STRIDE
                                      + ((lane >> 3) & 1)*16);

    float acc[8][4];
    #pragma unroll
    for (int nt=0;nt<8;nt++)
        #pragma unroll
        for (int q=0;q<4;q++) acc[nt][q] = 0.f;

    #pragma unroll
    for (int c = 0; c < 8; c++){
        if (c == 7) cpa_wait<0>(); else cpa_wait<1>();
        __syncwarp();
        uint32_t abase = awbase + (uint32_t)(c % 3)*1280;
        uint32_t bko = (uint32_t)c*64;
        #pragma unroll
        for (int ks = 0; ks < 2; ks++){
            unsigned a[4];
            ldm4(a[0], a[1], a[2], a[3], abase + aoff + ks*32);
            #pragma unroll
            for (int ntp = 0; ntp < 4; ntp++){
                unsigned bb[4];
                ldm4(bb[0], bb[1], bb[2], bb[3],
                     sbase + laneB + ntp*(16*B_STRIDE) + bko + ks*32);
                mma16(acc[2*ntp],   a, bb + 0);
                mma16(acc[2*ntp+1], a, bb + 2);
            }
        }
        if (c + 2 < 8) prefetch(c + 2, (c + 2) % 3);
    }

    // ---- epilogue: smem reused as per-warp slabs ----
    __syncthreads();
    const int gid = lane >> 2, tg = lane & 3;
    float* slab = (float*)sm + warp*1088;          // 16 rows x 68 floats
    #pragma unroll
    for (int nt = 0; nt < 8; nt++){
        int cc = nt*8 + tg*2;
        slab[gid*68 + cc]       = acc[nt][0];
        slab[gid*68 + cc + 1]   = acc[nt][1];
        slab[(gid+8)*68 + cc]   = acc[nt][2];
        slab[(gid+8)*68 + cc+1] = acc[nt][3];
    }
    __syncwarp();

    const int u = lane & 15, rh = lane >> 4;
    float4 b4 = make_float4(0.f,0.f,0.f,0.f);
    if (!Zout) b4 = ((const float4*)(bias + n0))[u];
    #pragma unroll 1
    for (int it = 0; it < 8; it++){
        int r = it*2 + rh;
        int grow = m0 + warp*16 + r;
        if (grow >= M) continue;
        float4 z = ((const float4*)(slab + r*68))[u];
        if (Zout){
            ((float4*)(Zout + (size_t)grow*zStride + n0))[u] = z;
        } else {
            z.x += b4.x; z.y += b4.y; z.z += b4.z; z.w += b4.w;
            if (Xadd){
                int xr = xIdx ? xIdx[grow] : grow;
                float4 x4 = ((const float4*)(Xadd + (size_t)xr*xStride + n0))[u];
                z.x += x4.x; z.y += x4.y; z.z += x4.z; z.w += x4.w;
            }
            int unit = (n0 >> 2) + u;
            float cp = 0.f;
            if (Cprev){
                int cr = cIdx ? cIdx[grow] : grow;
                cp = Cprev[(size_t)cr*256 + unit];
            }
            float cv = sigf(z.y)*cp + sigf(z.x)*tanhfast(z.z);
            float hv = sigf(z.w)*tanhfast(cv);
            if (halfH) ((__half*)HoutV)[(size_t)grow*hStride + hOff + unit] = __float2half(hv);
            else       ((float*)HoutV)[(size_t)grow*hStride + hOff + unit] = hv;
            if (Cout) Cout[(size_t)grow*256 + unit] = cv;
        }
    }
}

// ---------------- host ----------------
static void* sym(const void* s){ void* p = nullptr; cudaGetSymbolAddress(&p, s); return p; }

extern "C" void kernel_launch(void* const* d_in, const int* in_sizes, int n_in,
                              void* d_out, int out_size)
{
    const int*   src   = (const int*)  d_in[0];
    const int*   l2    = (const int*)  d_in[1];
    const int*   l3    = (const int*)  d_in[2];
    const float* embed = (const float*)d_in[3];
    const float* wihf  = (const float*)d_in[4];
    const float* whhf  = (const float*)d_in[5];
    const float* bihf  = (const float*)d_in[6];
    const float* bhhf  = (const float*)d_in[7];
    const float* wihb  = (const float*)d_in[8];
    const float* whhb  = (const float*)d_in[9];
    const float* bihb  = (const float*)d_in[10];
    const float* bhhb  = (const float*)d_in[11];
    float* out = (float*)d_out;

    cudaFuncSetAttribute(k_gemm, cudaFuncAttributeMaxDynamicSharedMemorySize, SMEMB);

    static cudaStream_t s1 = nullptr;
    static cudaEvent_t evPrep, evX0, evPf, evJoin;
    if (!s1){
        cudaStreamCreateWithFlags(&s1, cudaStreamNonBlocking);
        cudaEventCreateWithFlags(&evPrep, cudaEventDisableTiming);
        cudaEventCreateWithFlags(&evX0,  cudaEventDisableTiming);
        cudaEventCreateWithFlags(&evPf,  cudaEventDisableTiming);
        cudaEventCreateWithFlags(&evJoin,cudaEventDisableTiming);
    }

    __half *Wih2=(__half*)sym(g_Wih2);
    __half *Whhf=(__half*)sym(g_Whhf), *Whhb=(__half*)sym(g_Whhb);
    float *bf=(float*)sym(g_bf), *bb=(float*)sym(g_bb);
    __half *cat=(__half*)sym(g_cat);
    float *P=(float*)sym(g_P);
    __half *h1=(__half*)sym(g_h1), *h2=(__half*)sym(g_h2), *h3=(__half*)sym(g_h3);
    float *c1=(float*)sym(g_c1), *c2=(float*)sym(g_c2), *c3=(float*)sym(g_c3);
    float *HPb=(float*)sym(g_HPb);
    int *i01=(int*)sym(g_i01), *i3=(int*)sym(g_i3);
    __half *X0=(__half*)sym(g_X0);
    int *sidx=(int*)sym(g_sidx), *iF3=(int*)sym(g_iF3), *iFr=(int*)sym(g_iFr);
    __half *Ha=(__half*)sym(g_Ha), *Hc=(__half*)sym(g_Hc);
    float *Ca=(float*)sym(g_Ca), *Cc=(float*)sym(g_Cc);
    float *resF=(float*)sym(g_resF), *resB=(float*)sym(g_resB);
    int *cnt = nullptr; cudaGetSymbolAddress((void**)&cnt, g_cnt);

    __half *Wihf = Wih2;                 // rows 0-1023
    __half *Wihb = Wih2 + 1024*256;      // rows 1024-2047
    float  *P3base = P + (size_t)1001*2048;
    float  *Prbase = P + (size_t)1102*2048;

    dim3 gBig(256,16), gCat(9,32), gS1(1,16), gS101(1,16), gS1001(8,16);

    // ---- side stream s1: tree means (independent of weights) ----
    k_zero<<<1000,256,0,s1>>>();
    k_seg2<<<2048,256,0,s1>>>(embed, l2);
    k_lvl2<<<1001,256,0,s1>>>(l3);
    k_lvl3<<<101,256,0,s1>>>();
    k_root<<<1,256,0,s1>>>();
    k_bidx<<<5,256,0,s1>>>(l3);

    // ---- stream 0: dedup + weight prep + tokenize ----
    k_mapinit<<<391,256>>>();
    k_claim<<<128,256>>>(src);
    k_prep<<<1024,256>>>(wihf, whhf, bihf, bhhf, Wihf, Whhf, bf);
    k_prep<<<1024,256>>>(wihb, whhb, bihb, bhhb, Wihb, Whhb, bb);
    cudaEventRecord(evPrep, 0);
    k_tok2<<<1024,256>>>(l2, l3, embed);
    cudaEventRecord(evX0, 0);

    // BIG 1: forward step 1 (x=E[tok]), M = #unique (device)
    k_gemm<<<gBig,256,SMEMB>>>(X0, 0, Wihf, 0,0,0, bf, 0,0, Ha,256,0, Ca, 0,0, 1, NTOK, cnt);

    // ---- side stream s1: merged P-table GEMM + backward chain + bigB ----
    cudaStreamWaitEvent(s1, evPrep, 0);
    k_gemm<<<gCat,256,SMEMB,s1>>>(cat, 0, Wih2, 0,0,0, 0, 0,0, 0,0,0, 0, P, 2048, 0, 1104, 0);
    cudaEventRecord(evPf, s1);

    k_gemm<<<gS1   ,256,SMEMB,s1>>>(cat + (size_t)1102*256, 0, Wihb, 0,0,0,         bb, 0,0,    h1,256,0, c1, 0,0, 1, 2, 0);
    k_gemm<<<gS101 ,256,SMEMB,s1>>>(h1, i01, Whhb, P3base + 1024, 0, 2048,          bb, c1,i01, h2,256,0, c2, 0,0, 1, 101, 0);
    k_gemm<<<gS1001,256,SMEMB,s1>>>(h2, i3,  Whhb, P + 1024,      0, 2048,          bb, c2,i3,  h3,256,0, c3, 0,0, 1, 1001, 0);
    k_gemm<<<gS1001,256,SMEMB,s1>>>(h3, 0,   Whhb, 0,0,0, 0, 0,0, 0,0,0, 0, HPb, 1024, 0, 1001, 0);

    cudaStreamWaitEvent(s1, evX0, 0);
    k_gemm<<<gBig,256,SMEMB,s1>>>(X0, 0, Wihb, HPb, sidx, 1024, bb, c3, sidx, resB,256,0, 0, 0,0, 0, NTOK, cnt);
    cudaEventRecord(evJoin, s1);

    // ---- stream 0: forward steps 2-4 ----
    cudaStreamWaitEvent(0, evPf, 0);
    k_gemm<<<gBig,256,SMEMB>>>(Ha, 0, Whhf, P,      sidx, 2048, bf, Ca,0, Hc,256,0, Cc, 0,0, 1, NTOK, cnt);
    k_gemm<<<gBig,256,SMEMB>>>(Hc, 0, Whhf, P3base, iF3,  2048, bf, Cc,0, Ha,256,0, Ca, 0,0, 1, NTOK, cnt);
    k_gemm<<<gBig,256,SMEMB>>>(Ha, 0, Whhf, Prbase, iFr,  2048, bf, Ca,0, resF,256,0, 0, 0,0, 0, NTOK, cnt);

    // ---- expand compact results to all tokens ----
    cudaStreamWaitEvent(0, evJoin, 0);
    k_expand<<<4096,256>>>(src, out);
}